// round 16
// baseline (speedup 1.0000x reference)
#include <cuda_runtime.h>
#include <cuda_bf16.h>
#include <stdint.h>

#define B_       1024
#define NITEMS   50000
#define H1       600
#define H2       200
#define KPAD     50176   // 784 k64-tiles = 14*36 + 8*35 splits
#define XB_LD    KPAD
#define EB_LD    640
#define EB_ROWS  50048   // 391 * 128
#define W1T_ROWS 640

// ---------------- device scratch (static => zero-init; pads never written) ----------------
__device__ __nv_bfloat16 g_xb [(size_t)B_ * XB_LD];
__device__ __nv_bfloat16 g_w1t[(size_t)W1T_ROWS * XB_LD];
__device__ __nv_bfloat16 g_eb [(size_t)EB_ROWS * EB_LD];
__device__ __nv_bfloat16 g_h3b[(size_t)B_ * EB_LD];
__device__ float g_invn[B_];
__device__ float g_h1pre[B_ * H1];
__device__ float g_hsq[B_];
__device__ float g_esq[NITEMS];

// ---------------- asm helpers ----------------
__device__ __forceinline__ void mma_bf16(float* c, const uint32_t* a, const uint32_t* b) {
    asm volatile(
        "mma.sync.aligned.m16n8k16.row.col.f32.bf16.bf16.f32 "
        "{%0,%1,%2,%3},{%4,%5,%6,%7},{%8,%9},{%0,%1,%2,%3};\n"
        : "+f"(c[0]), "+f"(c[1]), "+f"(c[2]), "+f"(c[3])
        : "r"(a[0]), "r"(a[1]), "r"(a[2]), "r"(a[3]), "r"(b[0]), "r"(b[1]));
}
__device__ __forceinline__ uint32_t smem_u32(const void* p) {
    return (uint32_t)__cvta_generic_to_shared(p);
}
__device__ __forceinline__ void cp16(uint32_t dst, const void* src) {
    asm volatile("cp.async.cg.shared.global [%0], [%1], 16;\n" :: "r"(dst), "l"(src));
}
__device__ __forceinline__ void cp_commit() { asm volatile("cp.async.commit_group;\n"); }
template<int N> __device__ __forceinline__ void cp_wait() {
    asm volatile("cp.async.wait_group %0;\n" :: "n"(N));
}
__device__ __forceinline__ void ldsm4(uint32_t& r0, uint32_t& r1, uint32_t& r2, uint32_t& r3,
                                      uint32_t addr) {
    asm volatile("ldmatrix.sync.aligned.m8n8.x4.shared.b16 {%0,%1,%2,%3}, [%4];\n"
                 : "=r"(r0), "=r"(r1), "=r"(r2), "=r"(r3) : "r"(addr));
}
__device__ __forceinline__ void red_add_v2(float* ptr, float v0, float v1) {
    asm volatile("red.global.add.v2.f32 [%0], {%1, %2};"
                 :: "l"(ptr), "f"(v0), "f"(v1) : "memory");
}

// ---------------- GEMM building blocks ----------------
// Tile: BM=128, BN=128, BK=64, 256 threads (8 warps, each 32x64), 2 CTAs/SM.
// smem: rows of 64 halfs padded to 72 (144B) -> LDSM conflict-free.
#define STAGE_SZ  18432
#define B_BASE    55296
#define GEMM_SMEM (B_BASE + 3 * STAGE_SZ)   // 110592 bytes

__device__ __forceinline__ void load_stage(
    uint32_t sA, uint32_t sB,
    const __nv_bfloat16* __restrict__ A, size_t lda, int m0,
    const __nv_bfloat16* __restrict__ B, size_t ldb, int n0,
    int kg, int tid)
{
    #pragma unroll
    for (int i = 0; i < 4; i++) {
        int c = tid + i * 256;
        int r = c >> 3, cc = c & 7;
        cp16(sA + (uint32_t)(r * 144 + cc * 16), A + (size_t)(m0 + r) * lda + kg + cc * 8);
    }
    #pragma unroll
    for (int i = 0; i < 4; i++) {
        int c = tid + i * 256;
        int r = c >> 3, cc = c & 7;
        cp16(sB + (uint32_t)(r * 144 + cc * 16), B + (size_t)(n0 + r) * ldb + kg + cc * 8);
    }
}

template<int KMAX>
__device__ __forceinline__ void compute_stage_t(
    uint32_t sA, uint32_t sB, int wm, int wn, int lane, float acc[2][8][4])
{
    #pragma unroll
    for (int kk = 0; kk < KMAX; kk += 16) {
        uint32_t a[2][4];
        #pragma unroll
        for (int im = 0; im < 2; im++) {
            uint32_t addr = sA + (uint32_t)((wm + im * 16 + (lane & 15)) * 144
                                            + (kk + ((lane >> 4) << 3)) * 2);
            ldsm4(a[im][0], a[im][1], a[im][2], a[im][3], addr);
        }
        uint32_t b[8][2];
        #pragma unroll
        for (int ip = 0; ip < 4; ip++) {
            uint32_t addr = sB + (uint32_t)((wn + ip * 16 + ((lane >> 4) << 3) + (lane & 7)) * 144
                                            + (kk + (((lane >> 3) & 1) << 3)) * 2);
            uint32_t r0, r1, r2, r3;
            ldsm4(r0, r1, r2, r3, addr);
            b[ip * 2][0] = r0;     b[ip * 2][1] = r1;
            b[ip * 2 + 1][0] = r2; b[ip * 2 + 1][1] = r3;
        }
        #pragma unroll
        for (int im = 0; im < 2; im++)
            #pragma unroll
            for (int in = 0; in < 8; in++)
                mma_bf16(acc[im][in], a[im], b[in]);
    }
}

__device__ __forceinline__ void gemm_mainloop(
    uint32_t sb, int NT,
    const __nv_bfloat16* __restrict__ A, size_t lda, int m0,
    const __nv_bfloat16* __restrict__ B, size_t ldb, int n0,
    int kg0, int tid, int wm, int wn, int lane, float acc[2][8][4])
{
    load_stage(sb, sb + B_BASE, A, lda, m0, B, ldb, n0, kg0, tid);
    cp_commit();
    load_stage(sb + STAGE_SZ, sb + B_BASE + STAGE_SZ, A, lda, m0, B, ldb, n0, kg0 + 64, tid);
    cp_commit();

    int s = 0, s2 = 2;
    for (int kt = 0; kt < NT; kt++) {
        cp_wait<1>();
        __syncthreads();
        if (kt + 2 < NT)
            load_stage(sb + s2 * STAGE_SZ, sb + B_BASE + s2 * STAGE_SZ,
                       A, lda, m0, B, ldb, n0, kg0 + (kt + 2) * 64, tid);
        cp_commit();
        compute_stage_t<64>(sb + s * STAGE_SZ, sb + B_BASE + s * STAGE_SZ, wm, wn, lane, acc);
        s = (s == 2) ? 0 : s + 1;
        s2 = (s2 == 2) ? 0 : s2 + 1;
    }
}

// ---------------- GEMM1: h1pre += x_bf16 @ W1^T (split-K, vector red) ----------------
// grid (40, 22): x = m(8) + 8*n(5), y = ksplit; y<14 -> 36 tiles, else 35
// (14*36 + 8*35 = 784 covers KPAD). 880 CTAs = 2.97 waves at 2 CTAs/SM.
__global__ __launch_bounds__(256, 2) void k_gemm1() {
    extern __shared__ char smem[];
    uint32_t sb = smem_u32(smem);
    const int tid = threadIdx.x, lane = tid & 31, warp = tid >> 5;
    const int wm = (warp & 3) * 32, wn = (warp >> 2) * 64;
    const int gid = lane >> 2, tig = lane & 3;
    const int m0 = (blockIdx.x & 7) * 128;
    const int n0 = (blockIdx.x >> 3) * 128;
    const int y = blockIdx.y;
    const int NT = (y < 14) ? 36 : 35;
    const int kg0 = (y < 14) ? y * (36 * 64) : (14 * 36 + (y - 14) * 35) * 64;

    float acc[2][8][4];
    #pragma unroll
    for (int im = 0; im < 2; im++)
        #pragma unroll
        for (int in = 0; in < 8; in++)
            #pragma unroll
            for (int j = 0; j < 4; j++) acc[im][in][j] = 0.0f;

    gemm_mainloop(sb, NT, g_xb, XB_LD, m0, g_w1t, XB_LD, n0, kg0,
                  tid, wm, wn, lane, acc);

    #pragma unroll
    for (int im = 0; im < 2; im++) {
        int r = m0 + wm + im * 16 + gid;
        #pragma unroll
        for (int in = 0; in < 8; in++) {
            int c = n0 + wn + in * 8 + tig * 2;
            if (c < H1) {
                red_add_v2(&g_h1pre[r * H1 + c],       acc[im][in][0], acc[im][in][1]);
                red_add_v2(&g_h1pre[(r + 8) * H1 + c], acc[im][in][2], acc[im][in][3]);
            }
        }
    }
}

// ---------------- GEMM2: out = hsq[m] + esq[n] - 2*(h3 @ E^T) ----------------
// K_eff = 608: 9 full BK=64 tiles + 1 peeled half tile (kk<32).
__global__ __launch_bounds__(256, 2) void k_gemm2(float* __restrict__ out) {
    extern __shared__ char smem[];
    uint32_t sb = smem_u32(smem);
    const int tid = threadIdx.x, lane = tid & 31, warp = tid >> 5;
    const int wm = (warp & 3) * 32, wn = (warp >> 2) * 64;
    const int gid = lane >> 2, tig = lane & 3;
    const int m0 = blockIdx.x * 128;
    const int n0 = blockIdx.y * 128;

    float acc[2][8][4];
    #pragma unroll
    for (int im = 0; im < 2; im++)
        #pragma unroll
        for (int in = 0; in < 8; in++)
            #pragma unroll
            for (int j = 0; j < 4; j++) acc[im][in][j] = 0.0f;

    load_stage(sb, sb + B_BASE, g_h3b, EB_LD, m0, g_eb, EB_LD, n0, 0, tid);
    cp_commit();
    load_stage(sb + STAGE_SZ, sb + B_BASE + STAGE_SZ, g_h3b, EB_LD, m0, g_eb, EB_LD, n0, 64, tid);
    cp_commit();
    int s = 0, s2 = 2;
    for (int kt = 0; kt < 9; kt++) {
        cp_wait<1>();
        __syncthreads();
        if (kt + 2 < 10)
            load_stage(sb + s2 * STAGE_SZ, sb + B_BASE + s2 * STAGE_SZ,
                       g_h3b, EB_LD, m0, g_eb, EB_LD, n0, (kt + 2) * 64, tid);
        cp_commit();
        compute_stage_t<64>(sb + s * STAGE_SZ, sb + B_BASE + s * STAGE_SZ, wm, wn, lane, acc);
        s = (s == 2) ? 0 : s + 1;
        s2 = (s2 == 2) ? 0 : s2 + 1;
    }
    cp_wait<0>();
    __syncthreads();
    compute_stage_t<32>(sb + s * STAGE_SZ, sb + B_BASE + s * STAGE_SZ, wm, wn, lane, acc);

    #pragma unroll
    for (int im = 0; im < 2; im++) {
        int r = m0 + wm + im * 16 + gid;
        float hs0 = __ldg(&g_hsq[r]);
        float hs1 = __ldg(&g_hsq[r + 8]);
        #pragma unroll
        for (int in = 0; in < 8; in++) {
            int c = n0 + wn + in * 8 + tig * 2;
            if (c < NITEMS) {
                float e0 = __ldg(&g_esq[c]);
                float e1 = __ldg(&g_esq[c + 1]);
                float2 o0, o1;
                o0.x = hs0 + e0 - 2.0f * acc[im][in][0];
                o0.y = hs0 + e1 - 2.0f * acc[im][in][1];
                o1.x = hs1 + e0 - 2.0f * acc[im][in][2];
                o1.y = hs1 + e1 - 2.0f * acc[im][in][3];
                __stcs(reinterpret_cast<float2*>(&out[(size_t)r * NITEMS + c]), o0);
                __stcs(reinterpret_cast<float2*>(&out[(size_t)(r + 8) * NITEMS + c]), o1);
            }
        }
    }
}

// ---------------- fused preprocessing kernel ----------------
//   blocks [0, 1024)      : norm + fp32->bf16 convert of x row (dual accumulators)
//   blocks [.., +7840)    : W1 transpose-convert, 128k x 32n per block
//   blocks [.., +600)     : zero h1pre
#define NB_NORM 1024
#define NB_W1T  7840    // 392 k-tiles (128 wide) x 20 n-tiles (32 wide)
#define NB_ZERO 600
#define NB_PREP (NB_NORM + NB_W1T + NB_ZERO)

__global__ __launch_bounds__(256) void k_prep(const float* __restrict__ x,
                                              const float* __restrict__ W1) {
    const int bx = blockIdx.x;
    if (bx < NB_NORM) {
        int row = bx;
        const float* xr = x + (size_t)row * NITEMS;
        __nv_bfloat16* xbr = g_xb + (size_t)row * XB_LD;
        float s0 = 0.0f, s1 = 0.0f;
        for (int c = threadIdx.x; c < NITEMS / 8; c += 256) {
            float4 f0 = *reinterpret_cast<const float4*>(xr + c * 8);
            float4 f1 = *reinterpret_cast<const float4*>(xr + c * 8 + 4);
            s0 += f0.x * f0.x + f0.y * f0.y + f0.z * f0.z + f0.w * f0.w;
            s1 += f1.x * f1.x + f1.y * f1.y + f1.z * f1.z + f1.w * f1.w;
            __nv_bfloat162 p[4];
            p[0] = __floats2bfloat162_rn(f0.x, f0.y);
            p[1] = __floats2bfloat162_rn(f0.z, f0.w);
            p[2] = __floats2bfloat162_rn(f1.x, f1.y);
            p[3] = __floats2bfloat162_rn(f1.z, f1.w);
            *reinterpret_cast<uint4*>(xbr + c * 8) = *reinterpret_cast<uint4*>(p);
        }
        __shared__ float red[256];
        red[threadIdx.x] = s0 + s1;
        __syncthreads();
        for (int o = 128; o > 0; o >>= 1) {
            if (threadIdx.x < o) red[threadIdx.x] += red[threadIdx.x + o];
            __syncthreads();
        }
        if (threadIdx.x == 0) {
            float n = sqrtf(red[0]);
            g_invn[row] = 1.0f / fmaxf(n, 1e-12f);
        }
    } else if (bx < NB_NORM + NB_W1T) {
        // ---- W1 [k][n] fp32 -> g_w1t [n][k] bf16; 128k x 32n tile ----
        int i = bx - NB_NORM;
        int kt = i % 392, nt = i / 392;
        int k0 = kt * 128, n0 = nt * 32;
        __shared__ float t[128][33];
        int tr = threadIdx.x >> 5, tc = threadIdx.x & 31;
        #pragma unroll
        for (int j = 0; j < 16; j++) {
            int kr = k0 + j * 8 + tr;
            float v = 0.0f;
            if (kr < NITEMS && n0 + tc < H1) v = W1[(size_t)kr * H1 + n0 + tc];
            t[j * 8 + tr][tc] = v;
        }
        __syncthreads();
        int n_local = threadIdx.x >> 3;
        #pragma unroll
        for (int q = 0; q < 4; q++) {
            int kc = ((threadIdx.x & 7) + q * 8) * 4;
            __nv_bfloat16 v4[4];
            #pragma unroll
            for (int p = 0; p < 4; p++)
                v4[p] = __float2bfloat16_rn(t[kc + p][n_local]);
            *reinterpret_cast<uint2*>(&g_w1t[(size_t)(n0 + n_local) * XB_LD + k0 + kc]) =
                *reinterpret_cast<uint2*>(v4);
        }
    } else {
        int i = bx - NB_NORM - NB_W1T;
        int idx = i * 1024 + threadIdx.x * 4;
        *reinterpret_cast<float4*>(&g_h1pre[idx]) = make_float4(0.f, 0.f, 0.f, 0.f);
    }
}

// ---------------- fused MLP + E-conversion kernel ----------------
#define NB_MLP  256
#define NB_EB   6250

__global__ __launch_bounds__(256) void k_mlp(const float* __restrict__ W2,
                                             const float* __restrict__ b2,
                                             const float* __restrict__ W3,
                                             const float* __restrict__ b3,
                                             const float* __restrict__ b1,
                                             const float* __restrict__ E) {
    if (blockIdx.x >= NB_MLP) {
        int i = blockIdx.x - NB_MLP;
        int row = i * 8 + (threadIdx.x >> 5);
        int lane = threadIdx.x & 31;
        const float* er = E + (size_t)row * H1;
        __nv_bfloat16* eb = g_eb + (size_t)row * EB_LD;
        float s = 0.0f;
        for (int c = lane; c < H1 / 4; c += 32) {
            float4 v = *reinterpret_cast<const float4*>(er + c * 4);
            s += v.x * v.x + v.y * v.y + v.z * v.z + v.w * v.w;
            __nv_bfloat162 p0 = __floats2bfloat162_rn(v.x, v.y);
            __nv_bfloat162 p1 = __floats2bfloat162_rn(v.z, v.w);
            uint2 u;
            u.x = *reinterpret_cast<uint32_t*>(&p0);
            u.y = *reinterpret_cast<uint32_t*>(&p1);
            *reinterpret_cast<uint2*>(eb + c * 4) = u;
        }
        #pragma unroll
        for (int o = 16; o > 0; o >>= 1) s += __shfl_xor_sync(0xffffffffu, s, o);
        if (lane == 0) g_esq[row] = s;
        return;
    }

    const int m0 = blockIdx.x * 4;
    const int tid = threadIdx.x;
    __shared__ float a1[4][H1];
    __shared__ float h2s[4][H2];
    __shared__ float sred[4];

    for (int i = tid; i < 4 * H1; i += 256) {
        int r = i / H1, n = i - r * H1;
        a1[r][n] = tanhf(g_h1pre[(m0 + r) * H1 + n] * g_invn[m0 + r] + b1[n]);
    }
    if (tid < 4) sred[tid] = 0.0f;
    __syncthreads();

    if (tid < H2) {
        float acc[4] = {0.f, 0.f, 0.f, 0.f};
        for (int k = 0; k < H1; k++) {
            float w = W2[k * H2 + tid];
            #pragma unroll
            for (int r = 0; r < 4; r++) acc[r] = fmaf(a1[r][k], w, acc[r]);
        }
        float bb = b2[tid];
        #pragma unroll
        for (int r = 0; r < 4; r++) h2s[r][tid] = tanhf(acc[r] + bb);
    }
    __syncthreads();

    float ssq[4] = {0.f, 0.f, 0.f, 0.f};
    if (tid < H2) {
        float acc[4][3];
        #pragma unroll
        for (int r = 0; r < 4; r++)
            #pragma unroll
            for (int j = 0; j < 3; j++) acc[r][j] = 0.0f;
        for (int k = 0; k < H2; k++) {
            float w0 = W3[k * H1 + tid];
            float w1 = W3[k * H1 + tid + 200];
            float w2 = W3[k * H1 + tid + 400];
            #pragma unroll
            for (int r = 0; r < 4; r++) {
                float h = h2s[r][k];
                acc[r][0] = fmaf(h, w0, acc[r][0]);
                acc[r][1] = fmaf(h, w1, acc[r][1]);
                acc[r][2] = fmaf(h, w2, acc[r][2]);
            }
        }
        float bb0 = b3[tid], bb1 = b3[tid + 200], bb2 = b3[tid + 400];
        #pragma unroll
        for (int r = 0; r < 4; r++) {
            float h0 = tanhf(acc[r][0] + bb0);
            float h1 = tanhf(acc[r][1] + bb1);
            float h2v = tanhf(acc[r][2] + bb2);
            g_h3b[(size_t)(m0 + r) * EB_LD + tid]       = __float2bfloat16_rn(h0);
            g_h3b[(size_t)(m0 + r) * EB_LD + tid + 200] = __float2bfloat16_rn(h1);
            g_h3b[(size_t)(m0 + r) * EB_LD + tid + 400] = __float2bfloat16_rn(h2v);
            ssq[r] += h0 * h0 + h1 * h1 + h2v * h2v;
        }
    }
    #pragma unroll
    for (int r = 0; r < 4; r++) {
        float v = ssq[r];
        #pragma unroll
        for (int o = 16; o > 0; o >>= 1) v += __shfl_xor_sync(0xffffffffu, v, o);
        if ((tid & 31) == 0) atomicAdd(&sred[r], v);
    }
    __syncthreads();
    if (tid < 4) g_hsq[m0 + tid] = sred[tid];
}

// ---------------- launch ----------------
extern "C" void kernel_launch(void* const* d_in, const int* in_sizes, int n_in,
                              void* d_out, int out_size) {
    const float* x  = (const float*)d_in[0];
    const float* W1 = (const float*)d_in[1];
    const float* b1 = (const float*)d_in[2];
    const float* W2 = (const float*)d_in[3];
    const float* b2 = (const float*)d_in[4];
    const float* W3 = (const float*)d_in[5];
    const float* b3 = (const float*)d_in[6];
    const float* E  = (const float*)d_in[7];
    float* out = (float*)d_out;

    cudaFuncSetAttribute(k_gemm1, cudaFuncAttributeMaxDynamicSharedMemorySize, GEMM_SMEM);
    cudaFuncSetAttribute(k_gemm2, cudaFuncAttributeMaxDynamicSharedMemorySize, GEMM_SMEM);

    k_prep<<<NB_PREP, 256>>>(x, W1);
    k_gemm1<<<dim3(40, 22), 256, GEMM_SMEM>>>();
    k_mlp<<<NB_MLP + NB_EB, 256>>>(W2, b2, W3, b3, b1, E);
    k_gemm2<<<dim3(8, 391), 256, GEMM_SMEM>>>(out);
}

// round 17
// speedup vs baseline: 1.4099x; 1.4099x over previous
#include <cuda_runtime.h>
#include <cuda_bf16.h>
#include <stdint.h>

#define B_       1024
#define NITEMS   50000
#define H1       600
#define H2       200
#define KPAD     50176   // 784 k64-tiles = 28 + 27*28
#define XB_LD    KPAD
#define EB_LD    640
#define EB_ROWS  50048   // 391 * 128
#define W1T_ROWS 640

// ---------------- device scratch (static => zero-init; pads never written) ----------------
__device__ __nv_bfloat16 g_xb [(size_t)B_ * XB_LD];
__device__ __nv_bfloat16 g_w1t[(size_t)W1T_ROWS * XB_LD];
__device__ __nv_bfloat16 g_eb [(size_t)EB_ROWS * EB_LD];
__device__ __nv_bfloat16 g_h3b[(size_t)B_ * EB_LD];
__device__ float g_invn[B_];
__device__ float g_h1pre[B_ * H1];
__device__ float g_hsq[B_];
__device__ float g_esq[NITEMS];

// ---------------- asm helpers ----------------
__device__ __forceinline__ void mma_bf16(float* c, const uint32_t* a, const uint32_t* b) {
    asm volatile(
        "mma.sync.aligned.m16n8k16.row.col.f32.bf16.bf16.f32 "
        "{%0,%1,%2,%3},{%4,%5,%6,%7},{%8,%9},{%0,%1,%2,%3};\n"
        : "+f"(c[0]), "+f"(c[1]), "+f"(c[2]), "+f"(c[3])
        : "r"(a[0]), "r"(a[1]), "r"(a[2]), "r"(a[3]), "r"(b[0]), "r"(b[1]));
}
__device__ __forceinline__ uint32_t smem_u32(const void* p) {
    return (uint32_t)__cvta_generic_to_shared(p);
}
__device__ __forceinline__ void cp16(uint32_t dst, const void* src) {
    asm volatile("cp.async.cg.shared.global [%0], [%1], 16;\n" :: "r"(dst), "l"(src));
}
__device__ __forceinline__ void cp_commit() { asm volatile("cp.async.commit_group;\n"); }
template<int N> __device__ __forceinline__ void cp_wait() {
    asm volatile("cp.async.wait_group %0;\n" :: "n"(N));
}
__device__ __forceinline__ void ldsm4(uint32_t& r0, uint32_t& r1, uint32_t& r2, uint32_t& r3,
                                      uint32_t addr) {
    asm volatile("ldmatrix.sync.aligned.m8n8.x4.shared.b16 {%0,%1,%2,%3}, [%4];\n"
                 : "=r"(r0), "=r"(r1), "=r"(r2), "=r"(r3) : "r"(addr));
}

// ---------------- GEMM building blocks ----------------
// Tile: BM=128, BN=128, BK=64, 256 threads (8 warps, each 32x64), 2 CTAs/SM.
// smem: rows of 64 halfs padded to 72 (144B) -> LDSM conflict-free.
#define STAGE_SZ  18432
#define B_BASE    55296
#define GEMM_SMEM (B_BASE + 3 * STAGE_SZ)   // 110592 bytes

__device__ __forceinline__ void load_stage(
    uint32_t sA, uint32_t sB,
    const __nv_bfloat16* __restrict__ A, size_t lda, int m0,
    const __nv_bfloat16* __restrict__ B, size_t ldb, int n0,
    int kg, int tid)
{
    #pragma unroll
    for (int i = 0; i < 4; i++) {
        int c = tid + i * 256;
        int r = c >> 3, cc = c & 7;
        cp16(sA + (uint32_t)(r * 144 + cc * 16), A + (size_t)(m0 + r) * lda + kg + cc * 8);
    }
    #pragma unroll
    for (int i = 0; i < 4; i++) {
        int c = tid + i * 256;
        int r = c >> 3, cc = c & 7;
        cp16(sB + (uint32_t)(r * 144 + cc * 16), B + (size_t)(n0 + r) * ldb + kg + cc * 8);
    }
}

template<int KMAX>
__device__ __forceinline__ void compute_stage_t(
    uint32_t sA, uint32_t sB, int wm, int wn, int lane, float acc[2][8][4])
{
    #pragma unroll
    for (int kk = 0; kk < KMAX; kk += 16) {
        uint32_t a[2][4];
        #pragma unroll
        for (int im = 0; im < 2; im++) {
            uint32_t addr = sA + (uint32_t)((wm + im * 16 + (lane & 15)) * 144
                                            + (kk + ((lane >> 4) << 3)) * 2);
            ldsm4(a[im][0], a[im][1], a[im][2], a[im][3], addr);
        }
        uint32_t b[8][2];
        #pragma unroll
        for (int ip = 0; ip < 4; ip++) {
            uint32_t addr = sB + (uint32_t)((wn + ip * 16 + ((lane >> 4) << 3) + (lane & 7)) * 144
                                            + (kk + (((lane >> 3) & 1) << 3)) * 2);
            uint32_t r0, r1, r2, r3;
            ldsm4(r0, r1, r2, r3, addr);
            b[ip * 2][0] = r0;     b[ip * 2][1] = r1;
            b[ip * 2 + 1][0] = r2; b[ip * 2 + 1][1] = r3;
        }
        #pragma unroll
        for (int im = 0; im < 2; im++)
            #pragma unroll
            for (int in = 0; in < 8; in++)
                mma_bf16(acc[im][in], a[im], b[in]);
    }
}

__device__ __forceinline__ void gemm_mainloop(
    uint32_t sb, int NT,
    const __nv_bfloat16* __restrict__ A, size_t lda, int m0,
    const __nv_bfloat16* __restrict__ B, size_t ldb, int n0,
    int kg0, int tid, int wm, int wn, int lane, float acc[2][8][4])
{
    load_stage(sb, sb + B_BASE, A, lda, m0, B, ldb, n0, kg0, tid);
    cp_commit();
    load_stage(sb + STAGE_SZ, sb + B_BASE + STAGE_SZ, A, lda, m0, B, ldb, n0, kg0 + 64, tid);
    cp_commit();

    int s = 0, s2 = 2;
    for (int kt = 0; kt < NT; kt++) {
        cp_wait<1>();
        __syncthreads();
        if (kt + 2 < NT)
            load_stage(sb + s2 * STAGE_SZ, sb + B_BASE + s2 * STAGE_SZ,
                       A, lda, m0, B, ldb, n0, kg0 + (kt + 2) * 64, tid);
        cp_commit();
        compute_stage_t<64>(sb + s * STAGE_SZ, sb + B_BASE + s * STAGE_SZ, wm, wn, lane, acc);
        s = (s == 2) ? 0 : s + 1;
        s2 = (s2 == 2) ? 0 : s2 + 1;
    }
}

// ---------------- GEMM1: h1pre += x_bf16 @ W1^T (split-K, atomics) ----------------
// grid (40, 29): x = m(8) + 8*n(5), y = ksplit; y==0 -> 28 tiles, else 27 (28+27*28=784)
__global__ __launch_bounds__(256, 2) void k_gemm1() {
    extern __shared__ char smem[];
    uint32_t sb = smem_u32(smem);
    const int tid = threadIdx.x, lane = tid & 31, warp = tid >> 5;
    const int wm = (warp & 3) * 32, wn = (warp >> 2) * 64;
    const int gid = lane >> 2, tig = lane & 3;
    const int m0 = (blockIdx.x & 7) * 128;
    const int n0 = (blockIdx.x >> 3) * 128;
    const int y = blockIdx.y;
    const int NT = (y == 0) ? 28 : 27;
    const int kg0 = (y == 0) ? 0 : (28 + 27 * (y - 1)) * 64;

    float acc[2][8][4];
    #pragma unroll
    for (int im = 0; im < 2; im++)
        #pragma unroll
        for (int in = 0; in < 8; in++)
            #pragma unroll
            for (int j = 0; j < 4; j++) acc[im][in][j] = 0.0f;

    gemm_mainloop(sb, NT, g_xb, XB_LD, m0, g_w1t, XB_LD, n0, kg0,
                  tid, wm, wn, lane, acc);

    #pragma unroll
    for (int im = 0; im < 2; im++) {
        int r = m0 + wm + im * 16 + gid;
        #pragma unroll
        for (int in = 0; in < 8; in++) {
            int c = n0 + wn + in * 8 + tig * 2;
            if (c < H1) {
                atomicAdd(&g_h1pre[r * H1 + c],           acc[im][in][0]);
                atomicAdd(&g_h1pre[r * H1 + c + 1],       acc[im][in][1]);
                atomicAdd(&g_h1pre[(r + 8) * H1 + c],     acc[im][in][2]);
                atomicAdd(&g_h1pre[(r + 8) * H1 + c + 1], acc[im][in][3]);
            }
        }
    }
}

// ---------------- GEMM2: out = hsq[m] + esq[n] - 2*(h3 @ E^T) ----------------
// K_eff = 608: 9 full BK=64 tiles + 1 peeled half tile (kk<32).
__global__ __launch_bounds__(256, 2) void k_gemm2(float* __restrict__ out) {
    extern __shared__ char smem[];
    uint32_t sb = smem_u32(smem);
    const int tid = threadIdx.x, lane = tid & 31, warp = tid >> 5;
    const int wm = (warp & 3) * 32, wn = (warp >> 2) * 64;
    const int gid = lane >> 2, tig = lane & 3;
    const int m0 = blockIdx.x * 128;
    const int n0 = blockIdx.y * 128;

    float acc[2][8][4];
    #pragma unroll
    for (int im = 0; im < 2; im++)
        #pragma unroll
        for (int in = 0; in < 8; in++)
            #pragma unroll
            for (int j = 0; j < 4; j++) acc[im][in][j] = 0.0f;

    load_stage(sb, sb + B_BASE, g_h3b, EB_LD, m0, g_eb, EB_LD, n0, 0, tid);
    cp_commit();
    load_stage(sb + STAGE_SZ, sb + B_BASE + STAGE_SZ, g_h3b, EB_LD, m0, g_eb, EB_LD, n0, 64, tid);
    cp_commit();
    int s = 0, s2 = 2;
    for (int kt = 0; kt < 9; kt++) {
        cp_wait<1>();
        __syncthreads();
        if (kt + 2 < 10)
            load_stage(sb + s2 * STAGE_SZ, sb + B_BASE + s2 * STAGE_SZ,
                       g_h3b, EB_LD, m0, g_eb, EB_LD, n0, (kt + 2) * 64, tid);
        cp_commit();
        compute_stage_t<64>(sb + s * STAGE_SZ, sb + B_BASE + s * STAGE_SZ, wm, wn, lane, acc);
        s = (s == 2) ? 0 : s + 1;
        s2 = (s2 == 2) ? 0 : s2 + 1;
    }
    cp_wait<0>();
    __syncthreads();
    compute_stage_t<32>(sb + s * STAGE_SZ, sb + B_BASE + s * STAGE_SZ, wm, wn, lane, acc);

    #pragma unroll
    for (int im = 0; im < 2; im++) {
        int r = m0 + wm + im * 16 + gid;
        float hs0 = __ldg(&g_hsq[r]);
        float hs1 = __ldg(&g_hsq[r + 8]);
        #pragma unroll
        for (int in = 0; in < 8; in++) {
            int c = n0 + wn + in * 8 + tig * 2;
            if (c < NITEMS) {
                float e0 = __ldg(&g_esq[c]);
                float e1 = __ldg(&g_esq[c + 1]);
                float2 o0, o1;
                o0.x = hs0 + e0 - 2.0f * acc[im][in][0];
                o0.y = hs0 + e1 - 2.0f * acc[im][in][1];
                o1.x = hs1 + e0 - 2.0f * acc[im][in][2];
                o1.y = hs1 + e1 - 2.0f * acc[im][in][3];
                __stcs(reinterpret_cast<float2*>(&out[(size_t)r * NITEMS + c]), o0);
                __stcs(reinterpret_cast<float2*>(&out[(size_t)(r + 8) * NITEMS + c]), o1);
            }
        }
    }
}

// ---------------- fused preprocessing kernel ----------------
//   blocks [0, 1024)      : norm + fp32->bf16 convert of x row (dual accumulators)
//   blocks [.., +7840)    : W1 transpose-convert, 128k x 32n per block
//   blocks [.., +600)     : zero h1pre
#define NB_NORM 1024
#define NB_W1T  7840    // 392 k-tiles (128 wide) x 20 n-tiles (32 wide)
#define NB_ZERO 600
#define NB_PREP (NB_NORM + NB_W1T + NB_ZERO)

__global__ __launch_bounds__(256) void k_prep(const float* __restrict__ x,
                                              const float* __restrict__ W1) {
    const int bx = blockIdx.x;
    if (bx < NB_NORM) {
        int row = bx;
        const float* xr = x + (size_t)row * NITEMS;
        __nv_bfloat16* xbr = g_xb + (size_t)row * XB_LD;
        float s0 = 0.0f, s1 = 0.0f;
        for (int c = threadIdx.x; c < NITEMS / 8; c += 256) {
            float4 f0 = *reinterpret_cast<const float4*>(xr + c * 8);
            float4 f1 = *reinterpret_cast<const float4*>(xr + c * 8 + 4);
            s0 += f0.x * f0.x + f0.y * f0.y + f0.z * f0.z + f0.w * f0.w;
            s1 += f1.x * f1.x + f1.y * f1.y + f1.z * f1.z + f1.w * f1.w;
            __nv_bfloat162 p[4];
            p[0] = __floats2bfloat162_rn(f0.x, f0.y);
            p[1] = __floats2bfloat162_rn(f0.z, f0.w);
            p[2] = __floats2bfloat162_rn(f1.x, f1.y);
            p[3] = __floats2bfloat162_rn(f1.z, f1.w);
            *reinterpret_cast<uint4*>(xbr + c * 8) = *reinterpret_cast<uint4*>(p);
        }
        __shared__ float red[256];
        red[threadIdx.x] = s0 + s1;
        __syncthreads();
        for (int o = 128; o > 0; o >>= 1) {
            if (threadIdx.x < o) red[threadIdx.x] += red[threadIdx.x + o];
            __syncthreads();
        }
        if (threadIdx.x == 0) {
            float n = sqrtf(red[0]);
            g_invn[row] = 1.0f / fmaxf(n, 1e-12f);
        }
    } else if (bx < NB_NORM + NB_W1T) {
        // ---- W1 [k][n] fp32 -> g_w1t [n][k] bf16; 128k x 32n tile ----
        int i = bx - NB_NORM;
        int kt = i % 392, nt = i / 392;
        int k0 = kt * 128, n0 = nt * 32;
        __shared__ float t[128][33];
        int tr = threadIdx.x >> 5, tc = threadIdx.x & 31;
        #pragma unroll
        for (int j = 0; j < 16; j++) {
            int kr = k0 + j * 8 + tr;
            float v = 0.0f;
            if (kr < NITEMS && n0 + tc < H1) v = W1[(size_t)kr * H1 + n0 + tc];
            t[j * 8 + tr][tc] = v;
        }
        __syncthreads();
        int n_local = threadIdx.x >> 3;
        #pragma unroll
        for (int q = 0; q < 4; q++) {
            int kc = ((threadIdx.x & 7) + q * 8) * 4;
            __nv_bfloat16 v4[4];
            #pragma unroll
            for (int p = 0; p < 4; p++)
                v4[p] = __float2bfloat16_rn(t[kc + p][n_local]);
            *reinterpret_cast<uint2*>(&g_w1t[(size_t)(n0 + n_local) * XB_LD + k0 + kc]) =
                *reinterpret_cast<uint2*>(v4);
        }
    } else {
        int i = bx - NB_NORM - NB_W1T;
        int idx = i * 1024 + threadIdx.x * 4;
        *reinterpret_cast<float4*>(&g_h1pre[idx]) = make_float4(0.f, 0.f, 0.f, 0.f);
    }
}

// ---------------- fused MLP + E-conversion kernel ----------------
#define NB_MLP  256
#define NB_EB   6250

__global__ __launch_bounds__(256) void k_mlp(const float* __restrict__ W2,
                                             const float* __restrict__ b2,
                                             const float* __restrict__ W3,
                                             const float* __restrict__ b3,
                                             const float* __restrict__ b1,
                                             const float* __restrict__ E) {
    if (blockIdx.x >= NB_MLP) {
        int i = blockIdx.x - NB_MLP;
        int row = i * 8 + (threadIdx.x >> 5);
        int lane = threadIdx.x & 31;
        const float* er = E + (size_t)row * H1;
        __nv_bfloat16* eb = g_eb + (size_t)row * EB_LD;
        float s = 0.0f;
        for (int c = lane; c < H1 / 4; c += 32) {
            float4 v = *reinterpret_cast<const float4*>(er + c * 4);
            s += v.x * v.x + v.y * v.y + v.z * v.z + v.w * v.w;
            __nv_bfloat162 p0 = __floats2bfloat162_rn(v.x, v.y);
            __nv_bfloat162 p1 = __floats2bfloat162_rn(v.z, v.w);
            uint2 u;
            u.x = *reinterpret_cast<uint32_t*>(&p0);
            u.y = *reinterpret_cast<uint32_t*>(&p1);
            *reinterpret_cast<uint2*>(eb + c * 4) = u;
        }
        #pragma unroll
        for (int o = 16; o > 0; o >>= 1) s += __shfl_xor_sync(0xffffffffu, s, o);
        if (lane == 0) g_esq[row] = s;
        return;
    }

    const int m0 = blockIdx.x * 4;
    const int tid = threadIdx.x;
    __shared__ float a1[4][H1];
    __shared__ float h2s[4][H2];
    __shared__ float sred[4];

    for (int i = tid; i < 4 * H1; i += 256) {
        int r = i / H1, n = i - r * H1;
        a1[r][n] = tanhf(g_h1pre[(m0 + r) * H1 + n] * g_invn[m0 + r] + b1[n]);
    }
    if (tid < 4) sred[tid] = 0.0f;
    __syncthreads();

    if (tid < H2) {
        float acc[4] = {0.f, 0.f, 0.f, 0.f};
        for (int k = 0; k < H1; k++) {
            float w = W2[k * H2 + tid];
            #pragma unroll
            for (int r = 0; r < 4; r++) acc[r] = fmaf(a1[r][k], w, acc[r]);
        }
        float bb = b2[tid];
        #pragma unroll
        for (int r = 0; r < 4; r++) h2s[r][tid] = tanhf(acc[r] + bb);
    }
    __syncthreads();

    float ssq[4] = {0.f, 0.f, 0.f, 0.f};
    if (tid < H2) {
        float acc[4][3];
        #pragma unroll
        for (int r = 0; r < 4; r++)
            #pragma unroll
            for (int j = 0; j < 3; j++) acc[r][j] = 0.0f;
        for (int k = 0; k < H2; k++) {
            float w0 = W3[k * H1 + tid];
            float w1 = W3[k * H1 + tid + 200];
            float w2 = W3[k * H1 + tid + 400];
            #pragma unroll
            for (int r = 0; r < 4; r++) {
                float h = h2s[r][k];
                acc[r][0] = fmaf(h, w0, acc[r][0]);
                acc[r][1] = fmaf(h, w1, acc[r][1]);
                acc[r][2] = fmaf(h, w2, acc[r][2]);
            }
        }
        float bb0 = b3[tid], bb1 = b3[tid + 200], bb2 = b3[tid + 400];
        #pragma unroll
        for (int r = 0; r < 4; r++) {
            float h0 = tanhf(acc[r][0] + bb0);
            float h1 = tanhf(acc[r][1] + bb1);
            float h2v = tanhf(acc[r][2] + bb2);
            g_h3b[(size_t)(m0 + r) * EB_LD + tid]       = __float2bfloat16_rn(h0);
            g_h3b[(size_t)(m0 + r) * EB_LD + tid + 200] = __float2bfloat16_rn(h1);
            g_h3b[(size_t)(m0 + r) * EB_LD + tid + 400] = __float2bfloat16_rn(h2v);
            ssq[r] += h0 * h0 + h1 * h1 + h2v * h2v;
        }
    }
    #pragma unroll
    for (int r = 0; r < 4; r++) {
        float v = ssq[r];
        #pragma unroll
        for (int o = 16; o > 0; o >>= 1) v += __shfl_xor_sync(0xffffffffu, v, o);
        if ((tid & 31) == 0) atomicAdd(&sred[r], v);
    }
    __syncthreads();
    if (tid < 4) g_hsq[m0 + tid] = sred[tid];
}

// ---------------- launch ----------------
extern "C" void kernel_launch(void* const* d_in, const int* in_sizes, int n_in,
                              void* d_out, int out_size) {
    const float* x  = (const float*)d_in[0];
    const float* W1 = (const float*)d_in[1];
    const float* b1 = (const float*)d_in[2];
    const float* W2 = (const float*)d_in[3];
    const float* b2 = (const float*)d_in[4];
    const float* W3 = (const float*)d_in[5];
    const float* b3 = (const float*)d_in[6];
    const float* E  = (const float*)d_in[7];
    float* out = (float*)d_out;

    cudaFuncSetAttribute(k_gemm1, cudaFuncAttributeMaxDynamicSharedMemorySize, GEMM_SMEM);
    cudaFuncSetAttribute(k_gemm2, cudaFuncAttributeMaxDynamicSharedMemorySize, GEMM_SMEM);

    k_prep<<<NB_PREP, 256>>>(x, W1);
    k_gemm1<<<dim3(40, 29), 256, GEMM_SMEM>>>();
    k_mlp<<<NB_MLP + NB_EB, 256>>>(W2, b2, W3, b3, b1, E);
    k_gemm2<<<dim3(8, 391), 256, GEMM_SMEM>>>(out);
}